// round 13
// baseline (speedup 1.0000x reference)
#include <cuda_runtime.h>
#include <cstddef>
#include <cstdint>

#define C_DIM 64
#define H_DIM 150000
#define K_DIM 27
#define TILE_H 64
#define NBLK_H ((H_DIM + TILE_H - 1) / TILE_H)   // 2344

__device__ float g_xt[(size_t)H_DIM * C_DIM];   // 38.4 MB node-major x
__device__ float g_zero[C_DIM];                 // 256 B zeros

// ---------------------------------------------------------------------------
// Transpose x: (C, H) -> (H, C). 32h x 32c tile, block (32,8). (proven)
// ---------------------------------------------------------------------------
__global__ __launch_bounds__(256) void transpose_x_kernel(const float* __restrict__ x) {
    __shared__ float tile[32][33];
    const int hb = blockIdx.x * 32;
    const int cb = blockIdx.y * 32;
    const int tx = threadIdx.x, ty = threadIdx.y;

    const int h = hb + tx;
    if (h < H_DIM) {
        #pragma unroll
        for (int i = 0; i < 4; ++i) {
            const int c = cb + ty * 4 + i;
            tile[ty * 4 + i][tx] = x[(size_t)c * H_DIM + h];
        }
    }
    __syncthreads();

    const int j   = ty * 32 + tx;
    const int row = j / 8;
    const int cg  = j % 8;
    const int hh  = hb + row;
    if (hh < H_DIM) {
        float4 v = make_float4(tile[cg * 4 + 0][row], tile[cg * 4 + 1][row],
                               tile[cg * 4 + 2][row], tile[cg * 4 + 3][row]);
        *reinterpret_cast<float4*>(&g_xt[(size_t)hh * C_DIM + cb + cg * 4]) = v;
    }
}

// ---------------------------------------------------------------------------
// Pipelined staged gather — R8 geometry (TILE_H=64, 256 threads) with a
// TRIPLE-buffered cp.async pipeline: loads for k+1 and k+2 in flight, so the
// load consumed at iteration k was issued two iterations earlier (latency
// fully hidden behind two store phases + barriers).
//
// smem: 16B chunk (node j, logical chunk q=c>>2) at physical chunk
//       p = (q + (j>>2)) & 15.
// Load : 16B cp.async.cg, 16 lanes per 256B node row; STS conflict-free.
// Store: thread = (c, 4h) -> STG.128 (4 lines/warp-op), __stcs.
//        LDS 2-way worst case.
// ---------------------------------------------------------------------------
__global__ __launch_bounds__(256) void gather_kernel(const int* __restrict__ neigh,
                                                     float* __restrict__ out) {
    __shared__ float sm[3][TILE_H * C_DIM];       // 3 x 16 KB
    __shared__ int   sidx[TILE_H * K_DIM];        // 6.9 KB

    const int t  = threadIdx.x;
    const int hb = blockIdx.x * TILE_H;
    const int nvalid = (H_DIM - hb < TILE_H) ? (H_DIM - hb) * K_DIM : TILE_H * K_DIM;

    // coalesced copy of the contiguous neigh slab (64*27 = 1728 ints)
    #pragma unroll
    for (int r = 0; r < 7; ++r) {
        const int i = r * 256 + t;
        if (i < TILE_H * K_DIM)
            sidx[i] = (i < nvalid) ? neigh[(size_t)hb * K_DIM + i] : -1;
    }
    __syncthreads();

    uint32_t sm_base;
    asm volatile("{ .reg .u64 t64; cvta.to.shared.u64 t64, %1; cvt.u32.u64 %0, t64; }"
                 : "=r"(sm_base) : "l"((void*)sm));

    const int q  = t & 15;               // logical 16B chunk
    const int j0 = t >> 4;               // node base (0..15)

    // ---- load issuer: 1024 chunks = 4 cp.async per thread ----
    auto issue_load = [&](int k, int b) {
        #pragma unroll
        for (int r = 0; r < 4; ++r) {
            const int j = r * 16 + j0;                 // node in tile (0..63)
            const int node = sidx[j * K_DIM + k];
            const float* src = (node >= 0 ? g_xt + (size_t)node * C_DIM : g_zero) + q * 4;
            const int p = (q + (j >> 2)) & 15;
            const uint32_t dst = sm_base +
                (uint32_t)(((b * TILE_H + j) * C_DIM + p * 4) << 2);
            asm volatile("cp.async.cg.shared.global [%0], [%1], 16;" :: "r"(dst), "l"(src));
        }
        asm volatile("cp.async.commit_group;");
    };

    // prologue: two groups in flight
    issue_load(0, 0);
    issue_load(1, 1);

    const size_t KH = (size_t)K_DIM * H_DIM;
    const bool full = (hb + TILE_H) <= H_DIM;

    int bsel = 0;   // buffer of iteration k (k % 3)
    for (int k = 0; k < K_DIM; ++k) {
        if (k + 2 < K_DIM) {
            const int b2 = (bsel + 2 >= 3) ? bsel - 1 : bsel + 2;   // (k+2) % 3
            issue_load(k + 2, b2);
            asm volatile("cp.async.wait_group 2;");
        } else if (k + 1 < K_DIM) {
            asm volatile("cp.async.wait_group 1;");
        } else {
            asm volatile("cp.async.wait_group 0;");
        }
        __syncthreads();

        // store phase: 4096 floats = 4 float4 per thread
        const float* buf = sm[bsel];
        #pragma unroll
        for (int r = 0; r < 4; ++r) {
            const int h4 = t & 15;               // group of 4 h (0..15)
            const int c  = (t >> 4) + r * 16;    // channel (0..63)
            const int w  = (((c >> 2) + h4) & 15) * 4 + (c & 3);
            float4 v;
            v.x = buf[(h4 * 4 + 0) * C_DIM + w];
            v.y = buf[(h4 * 4 + 1) * C_DIM + w];
            v.z = buf[(h4 * 4 + 2) * C_DIM + w];
            v.w = buf[(h4 * 4 + 3) * C_DIM + w];
            const int h = hb + h4 * 4;
            float* dst = &out[(size_t)c * KH + (size_t)k * H_DIM + h];
            if (full) {
                __stcs(reinterpret_cast<float4*>(dst), v);
            } else {
                if (h + 0 < H_DIM) __stcs(dst + 0, v.x);
                if (h + 1 < H_DIM) __stcs(dst + 1, v.y);
                if (h + 2 < H_DIM) __stcs(dst + 2, v.z);
                if (h + 3 < H_DIM) __stcs(dst + 3, v.w);
            }
        }
        __syncthreads();   // buf fully consumed before its next overwrite
        bsel = (bsel + 1 == 3) ? 0 : bsel + 1;
    }
}

extern "C" void kernel_launch(void* const* d_in, const int* in_sizes, int n_in,
                              void* d_out, int out_size) {
    const float* x   = (const float*)d_in[0];   // (1, 64, 150000, 1) fp32
    const int*   nb  = (const int*)d_in[1];     // (150000, 27) int32
    float*       out = (float*)d_out;           // (1, 64, 27, 150000) fp32

    (void)in_sizes; (void)n_in; (void)out_size;

    {
        dim3 block(32, 8);
        dim3 grid((H_DIM + 31) / 32, C_DIM / 32);
        transpose_x_kernel<<<grid, block>>>(x);
    }
    {
        dim3 block(256);
        dim3 grid(NBLK_H);
        gather_kernel<<<grid, block>>>(nb, out);
    }
}

// round 16
// speedup vs baseline: 1.5812x; 1.5812x over previous
#include <cuda_runtime.h>
#include <cstddef>
#include <cstdint>

#define C_DIM 64
#define H_DIM 150000
#define K_DIM 27
#define TILE_H 64
#define NBLK_H ((H_DIM + TILE_H - 1) / TILE_H)   // 2344

__device__ float g_xt[(size_t)H_DIM * C_DIM];   // 38.4 MB node-major x

// ---------------------------------------------------------------------------
// Transpose x: (C, H) -> (H, C). 32h x 32c tile, block (32,8).
// PROVEN kernel from the 223.3us run — restored verbatim.
// ---------------------------------------------------------------------------
__global__ __launch_bounds__(256) void transpose_x_kernel(const float* __restrict__ x) {
    __shared__ float tile[32][33];
    const int hb = blockIdx.x * 32;
    const int cb = blockIdx.y * 32;
    const int tx = threadIdx.x, ty = threadIdx.y;

    const int h = hb + tx;
    if (h < H_DIM) {
        #pragma unroll
        for (int i = 0; i < 4; ++i) {
            const int c = cb + ty * 4 + i;
            tile[ty * 4 + i][tx] = x[(size_t)c * H_DIM + h];
        }
    }
    __syncthreads();

    const int j   = ty * 32 + tx;
    const int row = j / 8;
    const int cg  = j % 8;
    const int hh  = hb + row;
    if (hh < H_DIM) {
        float4 v = make_float4(tile[cg * 4 + 0][row], tile[cg * 4 + 1][row],
                               tile[cg * 4 + 2][row], tile[cg * 4 + 3][row]);
        *reinterpret_cast<float4*>(&g_xt[(size_t)hh * C_DIM + cb + cg * 4]) = v;
    }
}

// ---------------------------------------------------------------------------
// Pipelined staged gather — R8 geometry (TILE_H=64, 256 threads, 16 KB
// stages, wait-depth 1) with THREE buffers so only ONE __syncthreads per
// k-iteration is needed:
//   warp order at iter k: issue L(k+1)->B[(k+1)%3], wait_group 1, BARRIER,
//   store-read B[k%3].  The buffer overwritten by issue(k+1) was last read
//   at iter k-2, which every warp finished before passing barrier(k-1).
// Masked nodes: cp.async src-size 0 -> hardware zero-fill (no g_zero row).
// ---------------------------------------------------------------------------
__global__ __launch_bounds__(256) void gather_kernel(const int* __restrict__ neigh,
                                                     float* __restrict__ out) {
    __shared__ float sm[3][TILE_H * C_DIM];       // 3 x 16 KB
    __shared__ int   sidx[TILE_H * K_DIM];        // 6.9 KB

    const int t  = threadIdx.x;
    const int hb = blockIdx.x * TILE_H;
    const int nvalid = (H_DIM - hb < TILE_H) ? (H_DIM - hb) * K_DIM : TILE_H * K_DIM;

    // coalesced copy of the contiguous neigh slab (64*27 = 1728 ints)
    #pragma unroll
    for (int r = 0; r < 7; ++r) {
        const int i = r * 256 + t;
        if (i < TILE_H * K_DIM)
            sidx[i] = (i < nvalid) ? neigh[(size_t)hb * K_DIM + i] : -1;
    }
    __syncthreads();

    uint32_t sm_base;
    asm volatile("{ .reg .u64 t64; cvta.to.shared.u64 t64, %1; cvt.u32.u64 %0, t64; }"
                 : "=r"(sm_base) : "l"((void*)sm));

    const int q  = t & 15;               // logical 16B chunk
    const int j0 = t >> 4;               // node base (0..15)

    auto issue_load = [&](int k, int b) {
        #pragma unroll
        for (int r = 0; r < 4; ++r) {
            const int j = r * 16 + j0;                 // node in tile (0..63)
            const int node = sidx[j * K_DIM + k];
            const float* src = g_xt + (size_t)(node >= 0 ? node : 0) * C_DIM + q * 4;
            const int srcsz = (node >= 0) ? 16 : 0;    // 0 -> hw zero-fill
            const int p = (q + (j >> 2)) & 15;
            const uint32_t dst = sm_base +
                (uint32_t)(((b * TILE_H + j) * C_DIM + p * 4) << 2);
            asm volatile("cp.async.cg.shared.global [%0], [%1], 16, %2;"
                         :: "r"(dst), "l"(src), "r"(srcsz));
        }
        asm volatile("cp.async.commit_group;");
    };

    issue_load(0, 0);

    const size_t KH = (size_t)K_DIM * H_DIM;
    const bool full = (hb + TILE_H) <= H_DIM;

    int bsel = 0;    // k % 3
    int bnxt = 1;    // (k+1) % 3
    for (int k = 0; k < K_DIM; ++k) {
        if (k + 1 < K_DIM) {
            issue_load(k + 1, bnxt);
            asm volatile("cp.async.wait_group 1;");
        } else {
            asm volatile("cp.async.wait_group 0;");
        }
        __syncthreads();                 // single barrier per iteration

        const float* buf = sm[bsel];
        #pragma unroll
        for (int r = 0; r < 4; ++r) {
            const int h4 = t & 15;               // group of 4 h (0..15)
            const int c  = (t >> 4) + r * 16;    // channel (0..63)
            const int w  = (((c >> 2) + h4) & 15) * 4 + (c & 3);
            float4 v;
            v.x = buf[(h4 * 4 + 0) * C_DIM + w];
            v.y = buf[(h4 * 4 + 1) * C_DIM + w];
            v.z = buf[(h4 * 4 + 2) * C_DIM + w];
            v.w = buf[(h4 * 4 + 3) * C_DIM + w];
            const int h = hb + h4 * 4;
            float* dst = &out[(size_t)c * KH + (size_t)k * H_DIM + h];
            if (full) {
                __stcs(reinterpret_cast<float4*>(dst), v);
            } else {
                if (h + 0 < H_DIM) __stcs(dst + 0, v.x);
                if (h + 1 < H_DIM) __stcs(dst + 1, v.y);
                if (h + 2 < H_DIM) __stcs(dst + 2, v.z);
                if (h + 3 < H_DIM) __stcs(dst + 3, v.w);
            }
        }

        bsel = bnxt;
        bnxt = (bnxt + 1 == 3) ? 0 : bnxt + 1;
    }
}

extern "C" void kernel_launch(void* const* d_in, const int* in_sizes, int n_in,
                              void* d_out, int out_size) {
    const float* x   = (const float*)d_in[0];   // (1, 64, 150000, 1) fp32
    const int*   nb  = (const int*)d_in[1];     // (150000, 27) int32
    float*       out = (float*)d_out;           // (1, 64, 27, 150000) fp32

    (void)in_sizes; (void)n_in; (void)out_size;

    {
        dim3 block(32, 8);
        dim3 grid((H_DIM + 31) / 32, C_DIM / 32);
        transpose_x_kernel<<<grid, block>>>(x);
    }
    {
        dim3 block(256);
        dim3 grid(NBLK_H);
        gather_kernel<<<grid, block>>>(nb, out);
    }
}